// round 9
// baseline (speedup 1.0000x reference)
#include <cuda_runtime.h>
#include <cuda_bf16.h>
#include <cstdint>

// ============================================================================
// Problem constants
// ============================================================================
#define DFEAT 128
#define N_DST_MAX 100000
#define N_EDGE_MAX 512000

// static device scratch (no allocations allowed)
__device__ int g_cnt[N_DST_MAX];     // zero-init; fused gemm restores zeros
__device__ int g_rowptr[N_DST_MAX];  // absolute exclusive prefix
__device__ int g_cursor[N_DST_MAX];
__device__ int g_csr[N_EDGE_MAX];
__device__ int g_total;              // reset by hist_kernel each run

// ============================================================================
// Helpers
// ============================================================================
__device__ __forceinline__ uint32_t smem_to_u32(const void* smem_ptr) {
    uint32_t addr;
    asm("{ .reg .u64 tmp; cvta.to.shared.u64 tmp, %1; cvt.u32.u64 %0, tmp; }"
        : "=r"(addr) : "l"(smem_ptr));
    return addr;
}

#define LDSM_X4(r, addr) \
    asm volatile("ldmatrix.sync.aligned.m8n8.x4.shared.b16 {%0,%1,%2,%3}, [%4];" \
        : "=r"((r)[0]), "=r"((r)[1]), "=r"((r)[2]), "=r"((r)[3]) : "r"(addr))

#define MMA_BF16(d, a, b0, b1) \
    asm volatile("mma.sync.aligned.m16n8k16.row.col.f32.bf16.bf16.f32 " \
        "{%0,%1,%2,%3}, {%4,%5,%6,%7}, {%8,%9}, {%0,%1,%2,%3};" \
        : "+f"((d)[0]), "+f"((d)[1]), "+f"((d)[2]), "+f"((d)[3]) \
        : "r"((a)[0]), "r"((a)[1]), "r"((a)[2]), "r"((a)[3]), "r"(b0), "r"(b1))

__device__ __forceinline__ void split2(float f0, float f1, uint32_t& hi, uint32_t& lo) {
    __nv_bfloat16 h0 = __float2bfloat16(f0);
    __nv_bfloat16 h1 = __float2bfloat16(f1);
    __nv_bfloat16 l0 = __float2bfloat16(f0 - __bfloat162float(h0));
    __nv_bfloat16 l1 = __float2bfloat16(f1 - __bfloat162float(h1));
    hi = ((uint32_t)__bfloat16_as_ushort(h1) << 16) | (uint32_t)__bfloat16_as_ushort(h0);
    lo = ((uint32_t)__bfloat16_as_ushort(l1) << 16) | (uint32_t)__bfloat16_as_ushort(l0);
}

// ============================================================================
// CSR build: histogram -> single-pass scan -> fill   (3 launches)
// ============================================================================
__global__ void hist_kernel(const int* __restrict__ dst_idx, int n_edge) {
    int e = blockIdx.x * blockDim.x + threadIdx.x;
    if (e == 0) g_total = 0;  // consumed only by scan (next launch)
    if (e < n_edge) atomicAdd(&g_cnt[__ldg(dst_idx + e)], 1);
}

// per-4096-block scan; block offset claimed via atomicAdd on g_total.
// Block placement order is arbitrary but each row gets a contiguous CSR
// region, which is all aggregation needs.
__global__ void __launch_bounds__(1024) scan_block_kernel(int n) {
    __shared__ int ssum[1024];
    __shared__ int soff;
    int b = blockIdx.x, t = threadIdx.x;
    int base = b * 4096 + t * 4;
    int v[4], s = 0;
    #pragma unroll
    for (int j = 0; j < 4; j++) {
        v[j] = (base + j < n) ? g_cnt[base + j] : 0;
        s += v[j];
    }
    ssum[t] = s;
    __syncthreads();
    #pragma unroll
    for (int off = 1; off < 1024; off <<= 1) {
        int val = (t >= off) ? ssum[t - off] : 0;
        __syncthreads();
        ssum[t] += val;
        __syncthreads();
    }
    if (t == 1023) soff = atomicAdd(&g_total, ssum[1023]);
    __syncthreads();
    int run = ssum[t] - s + soff;  // absolute exclusive prefix
    #pragma unroll
    for (int j = 0; j < 4; j++) {
        if (base + j < n) { g_rowptr[base + j] = run; g_cursor[base + j] = run; }
        run += v[j];
    }
}

__global__ void fill_kernel(const int* __restrict__ src_idx,
                            const int* __restrict__ dst_idx, int n_edge) {
    int e = blockIdx.x * blockDim.x + threadIdx.x;
    if (e < n_edge) {
        int d = __ldg(dst_idx + e);
        int p = atomicAdd(&g_cursor[d], 1);
        g_csr[p] = __ldg(src_idx + e);
    }
}

// ============================================================================
// Fused aggregate + GEMM:
//   out[r,:] = (sum_{e in csr[r]} x[e] / degree[r]) @ W1^T + x[self_ids[r]] @ W2^T
// CTA: 256 threads (8 warps, 4x2), output tile 128x128, warp tile 32x64.
// kb=0: A = CSR-gathered, degree-normalized aggregate (built in-CTA,
//       warp-per-row fully coalesced gathers) vs B = W1.
// kb=1: A = x[self_ids] (warp-per-row)                vs B = W2.
// 3 hi/lo passes per kb: Ah*Bh + Al*Bh + Ah*Bl (fp32-accurate).
// ============================================================================
#define ROWPITCH 272
#define TILE_BYTES (128 * ROWPITCH)  // 34816
#define SM_A_HI 0
#define SM_A_LO (TILE_BYTES)
#define SM_B_HI (2 * TILE_BYTES)
#define SM_B_LO (3 * TILE_BYTES)
#define SMEM_TOTAL (4 * TILE_BYTES)  // 139264

__global__ void __launch_bounds__(256, 1) fused_agg_gemm_kernel(
    const float* __restrict__ x,
    const float* __restrict__ W1,
    const float* __restrict__ W2,
    const float* __restrict__ degree,
    const int* __restrict__ self_ids,
    float* __restrict__ out,
    int n_dst)
{
    extern __shared__ char smem[];
    uint32_t smem_base = smem_to_u32(smem);
    int tid = threadIdx.x;
    int wid = tid >> 5;
    int lane = tid & 31;
    int tile = blockIdx.x;

    int warp_m = (wid & 3) * 32;   // 0,32,64,96
    int warp_n = (wid >> 2) * 64;  // 0,64

    float acc[2][8][4];
    #pragma unroll
    for (int i = 0; i < 2; i++)
        #pragma unroll
        for (int j = 0; j < 8; j++)
            #pragma unroll
            for (int q = 0; q < 4; q++) acc[i][j][q] = 0.f;

    // per-lane ldmatrix base offsets
    uint32_t aoff = (uint32_t)(warp_m + (lane & 15)) * ROWPITCH
                  + ((lane & 16) ? 16u : 0u);
    uint32_t boff = (uint32_t)(warp_n + (lane & 7) + ((lane & 16) ? 8 : 0)) * ROWPITCH
                  + ((lane & 8) ? 16u : 0u);

    // B-load thread mapping: row = tid/2, half-row of 64 floats
    int lrow = tid >> 1;
    int lcol = (tid & 1) * 64;

    const float4* x4 = reinterpret_cast<const float4*>(x);

    #pragma unroll
    for (int kb = 0; kb < 2; kb++) {
        if (kb) __syncthreads();  // kb0 mma must finish reading A smem

        // ---- load B half-tile (W1 for kb=0, W2 for kb=1), layout [n][k] ----
        {
            const float* W = kb ? W2 : W1;
            const float4* src = reinterpret_cast<const float4*>(
                W + (size_t)lrow * DFEAT + lcol);
            #pragma unroll
            for (int j = 0; j < 16; j++) {
                float4 v = __ldg(src + j);
                uint32_t h0, l0, h1, l1;
                split2(v.x, v.y, h0, l0);
                split2(v.z, v.w, h1, l1);
                uint32_t o = (uint32_t)lrow * ROWPITCH + (uint32_t)(lcol + 4 * j) * 2;
                *reinterpret_cast<uint32_t*>(smem + SM_B_HI + o)     = h0;
                *reinterpret_cast<uint32_t*>(smem + SM_B_HI + o + 4) = h1;
                *reinterpret_cast<uint32_t*>(smem + SM_B_LO + o)     = l0;
                *reinterpret_cast<uint32_t*>(smem + SM_B_LO + o + 4) = l1;
            }
        }

        // ---- build A tile, warp-per-row (coalesced: lane = float4 index) ----
        for (int rr = wid; rr < 128; rr += 8) {
            int r = tile * 128 + rr;
            float4 a = make_float4(0.f, 0.f, 0.f, 0.f);
            if (r < n_dst) {
                if (kb == 0) {
                    int e   = __ldg(&g_rowptr[r]);
                    int cnt = __ldg(&g_cnt[r]);
                    int end = e + cnt;
                    __syncwarp();
                    if (lane == 0) g_cnt[r] = 0;  // reset for next replay
                    for (; e + 3 < end; e += 4) {
                        int s0 = __ldg(&g_csr[e]);
                        int s1 = __ldg(&g_csr[e + 1]);
                        int s2 = __ldg(&g_csr[e + 2]);
                        int s3 = __ldg(&g_csr[e + 3]);
                        float4 v0 = __ldg(x4 + (size_t)s0 * 32 + lane);
                        float4 v1 = __ldg(x4 + (size_t)s1 * 32 + lane);
                        float4 v2 = __ldg(x4 + (size_t)s2 * 32 + lane);
                        float4 v3 = __ldg(x4 + (size_t)s3 * 32 + lane);
                        a.x += v0.x + v1.x + v2.x + v3.x;
                        a.y += v0.y + v1.y + v2.y + v3.y;
                        a.z += v0.z + v1.z + v2.z + v3.z;
                        a.w += v0.w + v1.w + v2.w + v3.w;
                    }
                    for (; e < end; e++) {
                        int s0 = __ldg(&g_csr[e]);
                        float4 v0 = __ldg(x4 + (size_t)s0 * 32 + lane);
                        a.x += v0.x; a.y += v0.y; a.z += v0.z; a.w += v0.w;
                    }
                    float inv = 1.0f / __ldg(degree + r);
                    a.x *= inv; a.y *= inv; a.z *= inv; a.w *= inv;
                } else {
                    int sid = __ldg(self_ids + r);
                    a = __ldg(x4 + (size_t)sid * 32 + lane);
                }
            }
            uint32_t h0, l0, h1, l1;
            split2(a.x, a.y, h0, l0);
            split2(a.z, a.w, h1, l1);
            uint32_t o = (uint32_t)rr * ROWPITCH + (uint32_t)lane * 8;
            *reinterpret_cast<uint32_t*>(smem + SM_A_HI + o)     = h0;
            *reinterpret_cast<uint32_t*>(smem + SM_A_HI + o + 4) = h1;
            *reinterpret_cast<uint32_t*>(smem + SM_A_LO + o)     = l0;
            *reinterpret_cast<uint32_t*>(smem + SM_A_LO + o + 4) = l1;
        }
        __syncthreads();

        // ---- 3 passes x 8 k-steps of mma ----
        #pragma unroll
        for (int p = 0; p < 3; p++) {
            uint32_t abase = smem_base + (p == 1 ? SM_A_LO : SM_A_HI) + aoff;
            uint32_t bbase = smem_base + (p == 2 ? SM_B_LO : SM_B_HI) + boff;
            #pragma unroll
            for (int ks = 0; ks < 8; ks++) {
                uint32_t a0r[4], a1r[4];
                LDSM_X4(a0r, abase + ks * 32);
                LDSM_X4(a1r, abase + 16 * ROWPITCH + ks * 32);
                #pragma unroll
                for (int nf2 = 0; nf2 < 4; nf2++) {
                    uint32_t br[4];
                    LDSM_X4(br, bbase + nf2 * 16 * ROWPITCH + ks * 32);
                    MMA_BF16(acc[0][2 * nf2],     a0r, br[0], br[1]);
                    MMA_BF16(acc[0][2 * nf2 + 1], a0r, br[2], br[3]);
                    MMA_BF16(acc[1][2 * nf2],     a1r, br[0], br[1]);
                    MMA_BF16(acc[1][2 * nf2 + 1], a1r, br[2], br[3]);
                }
            }
        }
    }

    // ---- epilogue: c-frag (m = lane/4 + {0,8}, n = 2*(lane%4) + {0,1}) ----
    int rbase = tile * 128 + warp_m + (lane >> 2);
    int cbase = warp_n + (lane & 3) * 2;
    #pragma unroll
    for (int mf = 0; mf < 2; mf++) {
        #pragma unroll
        for (int nf = 0; nf < 8; nf++) {
            int r0 = rbase + mf * 16;
            int c  = cbase + nf * 8;
            if (r0 < n_dst) {
                float2* p = reinterpret_cast<float2*>(out + (size_t)r0 * DFEAT + c);
                *p = make_float2(acc[mf][nf][0], acc[mf][nf][1]);
            }
            if (r0 + 8 < n_dst) {
                float2* p = reinterpret_cast<float2*>(out + (size_t)(r0 + 8) * DFEAT + c);
                *p = make_float2(acc[mf][nf][2], acc[mf][nf][3]);
            }
        }
    }
}

// ============================================================================
// kernel_launch
// inputs: 0:x [N_SRC*128 f32]  1:W1 [128*128 f32]  2:W2 [128*128 f32]
//         3:degree [N_DST f32] 4:src_idx [N_EDGE i32] 5:dst_idx [N_EDGE i32]
//         6:self_ids [N_DST i32]       output: [N_DST*128 f32]
// ============================================================================
extern "C" void kernel_launch(void* const* d_in, const int* in_sizes, int n_in,
                              void* d_out, int out_size) {
    const float* x        = (const float*)d_in[0];
    const float* W1       = (const float*)d_in[1];
    const float* W2       = (const float*)d_in[2];
    const float* degree   = (const float*)d_in[3];
    const int*   src_idx  = (const int*)d_in[4];
    const int*   dst_idx  = (const int*)d_in[5];
    const int*   self_ids = (const int*)d_in[6];
    float* out = (float*)d_out;

    int n_dst  = in_sizes[3];
    int n_edge = in_sizes[4];

    // CSR build (g_cnt zeroed by the fused kernel of the previous run / static init)
    hist_kernel<<<(n_edge + 255) / 256, 256>>>(dst_idx, n_edge);
    int nblocks = (n_dst + 4095) / 4096;
    scan_block_kernel<<<nblocks, 1024>>>(n_dst);
    fill_kernel<<<(n_edge + 255) / 256, 256>>>(src_idx, dst_idx, n_edge);

    // Fused aggregate + GEMM
    static bool attr_set = false;
    if (!attr_set) {
        cudaFuncSetAttribute(fused_agg_gemm_kernel,
                             cudaFuncAttributeMaxDynamicSharedMemorySize, SMEM_TOTAL);
        attr_set = true;
    }
    fused_agg_gemm_kernel<<<(n_dst + 127) / 128, 256, SMEM_TOTAL>>>(
        x, W1, W2, degree, self_ids, out, n_dst);
}

// round 12
// speedup vs baseline: 2.2873x; 2.2873x over previous
#include <cuda_runtime.h>
#include <cuda_bf16.h>
#include <cstdint>

// ============================================================================
// Problem constants
// ============================================================================
#define DFEAT 128
#define N_DST_MAX 100000
#define N_EDGE_MAX 512000

// static device scratch (no allocations allowed)
__device__ __align__(16) float g_agg[(size_t)N_DST_MAX * DFEAT];  // normalized agg
__device__ int g_cnt[N_DST_MAX];     // zero-init; agg_kernel restores zeros
__device__ int g_rowptr[N_DST_MAX];  // absolute exclusive prefix
__device__ int g_cursor[N_DST_MAX];
__device__ int g_csr[N_EDGE_MAX];
__device__ int g_total;              // reset by hist_kernel each run

// ============================================================================
// Helpers
// ============================================================================
__device__ __forceinline__ uint32_t smem_to_u32(const void* smem_ptr) {
    uint32_t addr;
    asm("{ .reg .u64 tmp; cvta.to.shared.u64 tmp, %1; cvt.u32.u64 %0, tmp; }"
        : "=r"(addr) : "l"(smem_ptr));
    return addr;
}

#define LDSM_X4(r, addr) \
    asm volatile("ldmatrix.sync.aligned.m8n8.x4.shared.b16 {%0,%1,%2,%3}, [%4];" \
        : "=r"((r)[0]), "=r"((r)[1]), "=r"((r)[2]), "=r"((r)[3]) : "r"(addr))

#define MMA_BF16(d, a, b0, b1) \
    asm volatile("mma.sync.aligned.m16n8k16.row.col.f32.bf16.bf16.f32 " \
        "{%0,%1,%2,%3}, {%4,%5,%6,%7}, {%8,%9}, {%0,%1,%2,%3};" \
        : "+f"((d)[0]), "+f"((d)[1]), "+f"((d)[2]), "+f"((d)[3]) \
        : "r"((a)[0]), "r"((a)[1]), "r"((a)[2]), "r"((a)[3]), "r"(b0), "r"(b1))

__device__ __forceinline__ void split2(float f0, float f1, uint32_t& hi, uint32_t& lo) {
    __nv_bfloat16 h0 = __float2bfloat16(f0);
    __nv_bfloat16 h1 = __float2bfloat16(f1);
    __nv_bfloat16 l0 = __float2bfloat16(f0 - __bfloat162float(h0));
    __nv_bfloat16 l1 = __float2bfloat16(f1 - __bfloat162float(h1));
    hi = ((uint32_t)__bfloat16_as_ushort(h1) << 16) | (uint32_t)__bfloat16_as_ushort(h0);
    lo = ((uint32_t)__bfloat16_as_ushort(l1) << 16) | (uint32_t)__bfloat16_as_ushort(l0);
}

// ============================================================================
// CSR build: histogram -> single-pass scan -> fill   (3 launches)
// ============================================================================
__global__ void hist_kernel(const int* __restrict__ dst_idx, int n_edge) {
    int e = blockIdx.x * blockDim.x + threadIdx.x;
    if (e == 0) g_total = 0;  // consumed only by scan (next launch)
    if (e < n_edge) atomicAdd(&g_cnt[__ldg(dst_idx + e)], 1);
}

// per-4096-block scan; block offset claimed via atomicAdd on g_total.
// Block placement order is arbitrary but each row still gets a contiguous
// CSR region, which is all aggregation needs.
__global__ void __launch_bounds__(1024) scan_block_kernel(int n) {
    __shared__ int ssum[1024];
    __shared__ int soff;
    int b = blockIdx.x, t = threadIdx.x;
    int base = b * 4096 + t * 4;
    int v[4], s = 0;
    #pragma unroll
    for (int j = 0; j < 4; j++) {
        v[j] = (base + j < n) ? g_cnt[base + j] : 0;
        s += v[j];
    }
    ssum[t] = s;
    __syncthreads();
    #pragma unroll
    for (int off = 1; off < 1024; off <<= 1) {
        int val = (t >= off) ? ssum[t - off] : 0;
        __syncthreads();
        ssum[t] += val;
        __syncthreads();
    }
    if (t == 1023) soff = atomicAdd(&g_total, ssum[1023]);
    __syncthreads();
    int run = ssum[t] - s + soff;  // absolute exclusive prefix
    #pragma unroll
    for (int j = 0; j < 4; j++) {
        if (base + j < n) { g_rowptr[base + j] = run; g_cursor[base + j] = run; }
        run += v[j];
    }
}

__global__ void fill_kernel(const int* __restrict__ src_idx,
                            const int* __restrict__ dst_idx, int n_edge) {
    int e = blockIdx.x * blockDim.x + threadIdx.x;
    if (e < n_edge) {
        int d = __ldg(dst_idx + e);
        int p = atomicAdd(&g_cursor[d], 1);
        g_csr[p] = __ldg(src_idx + e);
    }
}

// ============================================================================
// Aggregation: one warp per dst row, lanes hold a float4 each (round-4 shape:
// measured best). Writes degree-normalized agg with plain stores; resets
// g_cnt for the next graph replay. unroll-4 gather for MLP.
// ============================================================================
__global__ void __launch_bounds__(256) agg_kernel(
    const float* __restrict__ x,
    const float* __restrict__ degree,
    int n_dst)
{
    int t = blockIdx.x * blockDim.x + threadIdx.x;
    int r = t >> 5;
    if (r >= n_dst) return;
    int lane = t & 31;
    int start = __ldg(&g_rowptr[r]);
    int c = __ldg(&g_cnt[r]);
    __syncwarp();
    if (lane == 0) g_cnt[r] = 0;  // reset for next replay
    const float4* x4 = reinterpret_cast<const float4*>(x);
    float4 acc = make_float4(0.f, 0.f, 0.f, 0.f);
    int e = start, end = start + c;
    for (; e + 3 < end; e += 4) {
        int s0 = __ldg(&g_csr[e]);
        int s1 = __ldg(&g_csr[e + 1]);
        int s2 = __ldg(&g_csr[e + 2]);
        int s3 = __ldg(&g_csr[e + 3]);
        float4 v0 = __ldg(x4 + (size_t)s0 * 32 + lane);
        float4 v1 = __ldg(x4 + (size_t)s1 * 32 + lane);
        float4 v2 = __ldg(x4 + (size_t)s2 * 32 + lane);
        float4 v3 = __ldg(x4 + (size_t)s3 * 32 + lane);
        acc.x += v0.x + v1.x + v2.x + v3.x;
        acc.y += v0.y + v1.y + v2.y + v3.y;
        acc.z += v0.z + v1.z + v2.z + v3.z;
        acc.w += v0.w + v1.w + v2.w + v3.w;
    }
    for (; e < end; e++) {
        int s0 = __ldg(&g_csr[e]);
        float4 v0 = __ldg(x4 + (size_t)s0 * 32 + lane);
        acc.x += v0.x; acc.y += v0.y; acc.z += v0.z; acc.w += v0.w;
    }
    float inv = 1.0f / __ldg(degree + r);
    acc.x *= inv; acc.y *= inv; acc.z *= inv; acc.w *= inv;
    reinterpret_cast<float4*>(g_agg)[(size_t)r * 32 + lane] = acc;
}

// ============================================================================
// Fused GEMM via mma.sync bf16 + hi/lo 3-term split (round-4 shape: measured
// best).  out[r,:] = agg_norm[r,:] @ W1^T + x[self_ids[r],:] @ W2^T
// CTA: 256 threads (8 warps, 4x2), output tile 128x128, warp tile 32x64.
// ============================================================================
#define ROWPITCH 272
#define TILE_BYTES (128 * ROWPITCH)  // 34816
#define SM_A_HI 0
#define SM_A_LO (TILE_BYTES)
#define SM_B_HI (2 * TILE_BYTES)
#define SM_B_LO (3 * TILE_BYTES)
#define SMEM_TOTAL (4 * TILE_BYTES)  // 139264

__global__ void __launch_bounds__(256, 1) fused_gemm_kernel(
    const float* __restrict__ x,
    const float* __restrict__ W1,
    const float* __restrict__ W2,
    const int* __restrict__ self_ids,
    float* __restrict__ out,
    int n_dst)
{
    extern __shared__ char smem[];
    uint32_t smem_base = smem_to_u32(smem);
    int tid = threadIdx.x;
    int wid = tid >> 5;
    int lane = tid & 31;
    int tile = blockIdx.x;

    int warp_m = (wid & 3) * 32;   // 0,32,64,96
    int warp_n = (wid >> 2) * 64;  // 0,64

    float acc[2][8][4];
    #pragma unroll
    for (int i = 0; i < 2; i++)
        #pragma unroll
        for (int j = 0; j < 8; j++)
            #pragma unroll
            for (int q = 0; q < 4; q++) acc[i][j][q] = 0.f;

    // per-lane ldmatrix base offsets
    uint32_t aoff = (uint32_t)(warp_m + (lane & 15)) * ROWPITCH
                  + ((lane & 16) ? 16u : 0u);
    uint32_t boff = (uint32_t)(warp_n + (lane & 7) + ((lane & 16) ? 8 : 0)) * ROWPITCH
                  + ((lane & 8) ? 16u : 0u);

    int lrow = tid >> 1;
    int lcol = (tid & 1) * 64;

    #pragma unroll
    for (int kb = 0; kb < 2; kb++) {
        if (kb) __syncthreads();

        // ---- load A half-tile (agg_norm for kb=0, x[self] for kb=1) ----
        {
            int r = tile * 128 + lrow;
            const float4* src = nullptr;
            if (r < n_dst) {
                if (kb == 0) {
                    src = reinterpret_cast<const float4*>(g_agg + (size_t)r * DFEAT + lcol);
                } else {
                    int sid = __ldg(self_ids + r);
                    src = reinterpret_cast<const float4*>(x + (size_t)sid * DFEAT + lcol);
                }
            }
            #pragma unroll
            for (int j = 0; j < 16; j++) {
                float4 v = make_float4(0.f, 0.f, 0.f, 0.f);
                if (src) v = __ldg(src + j);
                uint32_t h0, l0, h1, l1;
                split2(v.x, v.y, h0, l0);
                split2(v.z, v.w, h1, l1);
                uint32_t o = (uint32_t)lrow * ROWPITCH + (uint32_t)(lcol + 4 * j) * 2;
                *reinterpret_cast<uint32_t*>(smem + SM_A_HI + o)     = h0;
                *reinterpret_cast<uint32_t*>(smem + SM_A_HI + o + 4) = h1;
                *reinterpret_cast<uint32_t*>(smem + SM_A_LO + o)     = l0;
                *reinterpret_cast<uint32_t*>(smem + SM_A_LO + o + 4) = l1;
            }
        }
        // ---- load B half-tile (W1 for kb=0, W2 for kb=1), layout [n][k] ----
        {
            const float* W = kb ? W2 : W1;
            const float4* src = reinterpret_cast<const float4*>(
                W + (size_t)lrow * DFEAT + lcol);
            #pragma unroll
            for (int j = 0; j < 16; j++) {
                float4 v = __ldg(src + j);
                uint32_t h0, l0, h1, l1;
                split2(v.x, v.y, h0, l0);
                split2(v.z, v.w, h1, l1);
                uint32_t o = (uint32_t)lrow * ROWPITCH + (uint32_t)(lcol + 4 * j) * 2;
                *reinterpret_cast<uint32_t*>(smem + SM_B_HI + o)     = h0;
                *reinterpret_cast<uint32_t*>(smem + SM_B_HI + o + 4) = h1;
                *reinterpret_cast<uint32_t*>(smem + SM_B_LO + o)     = l0;
                *reinterpret_cast<uint32_t*>(smem + SM_B_LO + o + 4) = l1;
            }
        }
        __syncthreads();

        // ---- 3 passes x 8 k-steps of mma ----
        #pragma unroll
        for (int p = 0; p < 3; p++) {
            uint32_t abase = smem_base + (p == 1 ? SM_A_LO : SM_A_HI) + aoff;
            uint32_t bbase = smem_base + (p == 2 ? SM_B_LO : SM_B_HI) + boff;
            #pragma unroll
            for (int ks = 0; ks < 8; ks++) {
                uint32_t a0r[4], a1r[4];
                LDSM_X4(a0r, abase + ks * 32);
                LDSM_X4(a1r, abase + 16 * ROWPITCH + ks * 32);
                #pragma unroll
                for (int nf2 = 0; nf2 < 4; nf2++) {
                    uint32_t br[4];
                    LDSM_X4(br, bbase + nf2 * 16 * ROWPITCH + ks * 32);
                    MMA_BF16(acc[0][2 * nf2],     a0r, br[0], br[1]);
                    MMA_BF16(acc[0][2 * nf2 + 1], a0r, br[2], br[3]);
                    MMA_BF16(acc[1][2 * nf2],     a1r, br[0], br[1]);
                    MMA_BF16(acc[1][2 * nf2 + 1], a1r, br[2], br[3]);
                }
            }
        }
    }

    // ---- epilogue ----
    int rbase = tile * 128 + warp_m + (lane >> 2);
    int cbase = warp_n + (lane & 3) * 2;
    #pragma unroll
    for (int mf = 0; mf < 2; mf++) {
        #pragma unroll
        for (int nf = 0; nf < 8; nf++) {
            int r0 = rbase + mf * 16;
            int c  = cbase + nf * 8;
            if (r0 < n_dst) {
                float2* p = reinterpret_cast<float2*>(out + (size_t)r0 * DFEAT + c);
                *p = make_float2(acc[mf][nf][0], acc[mf][nf][1]);
            }
            if (r0 + 8 < n_dst) {
                float2* p = reinterpret_cast<float2*>(out + (size_t)(r0 + 8) * DFEAT + c);
                *p = make_float2(acc[mf][nf][2], acc[mf][nf][3]);
            }
        }
    }
}

// ============================================================================
// kernel_launch
// inputs: 0:x [N_SRC*128 f32]  1:W1 [128*128 f32]  2:W2 [128*128 f32]
//         3:degree [N_DST f32] 4:src_idx [N_EDGE i32] 5:dst_idx [N_EDGE i32]
//         6:self_ids [N_DST i32]       output: [N_DST*128 f32]
// ============================================================================
extern "C" void kernel_launch(void* const* d_in, const int* in_sizes, int n_in,
                              void* d_out, int out_size) {
    const float* x        = (const float*)d_in[0];
    const float* W1       = (const float*)d_in[1];
    const float* W2       = (const float*)d_in[2];
    const float* degree   = (const float*)d_in[3];
    const int*   src_idx  = (const int*)d_in[4];
    const int*   dst_idx  = (const int*)d_in[5];
    const int*   self_ids = (const int*)d_in[6];
    float* out = (float*)d_out;

    int n_dst  = in_sizes[3];
    int n_edge = in_sizes[4];

    // CSR build (g_cnt zeroed by agg_kernel of the previous run / static init)
    hist_kernel<<<(n_edge + 255) / 256, 256>>>(dst_idx, n_edge);
    int nblocks = (n_dst + 4095) / 4096;
    scan_block_kernel<<<nblocks, 1024>>>(n_dst);
    fill_kernel<<<(n_edge + 255) / 256, 256>>>(src_idx, dst_idx, n_edge);

    // Aggregation (1 warp / dst row — measured-best shape)
    long long tot = (long long)n_dst * 32;
    agg_kernel<<<(int)((tot + 255) / 256), 256>>>(x, degree, n_dst);

    // Fused GEMM (measured-best shape)
    static bool attr_set = false;
    if (!attr_set) {
        cudaFuncSetAttribute(fused_gemm_kernel,
                             cudaFuncAttributeMaxDynamicSharedMemorySize, SMEM_TOTAL);
        attr_set = true;
    }
    fused_gemm_kernel<<<(n_dst + 127) / 128, 256, SMEM_TOTAL>>>(
        x, W1, W2, self_ids, out, n_dst);
}

// round 15
// speedup vs baseline: 2.4684x; 1.0792x over previous
#include <cuda_runtime.h>
#include <cuda_bf16.h>
#include <cstdint>

// ============================================================================
// Problem constants
// ============================================================================
#define DFEAT 128
#define N_DST_MAX 100000
#define N_EDGE_MAX 512000

// static device scratch (no allocations allowed)
__device__ int g_cnt[N_DST_MAX];     // zero-init; aggself_kernel restores zeros
__device__ int g_rowptr[N_DST_MAX];  // absolute exclusive prefix
__device__ int g_cursor[N_DST_MAX];
__device__ int g_csr[N_EDGE_MAX];
__device__ int g_total;              // reset by hist_kernel each run

// pre-split bf16 operands (hi/lo), packed [row][k] (128 bf16 = 256B per row)
__device__ __align__(16) uint32_t g_aggh[(size_t)N_DST_MAX * 64];
__device__ __align__(16) uint32_t g_aggl[(size_t)N_DST_MAX * 64];
__device__ __align__(16) uint32_t g_selfh[(size_t)N_DST_MAX * 64];
__device__ __align__(16) uint32_t g_selfl[(size_t)N_DST_MAX * 64];
__device__ __align__(16) uint32_t g_bh[2 * 128 * 64];  // [kb][n][k/2]
__device__ __align__(16) uint32_t g_bl[2 * 128 * 64];

// ============================================================================
// Helpers
// ============================================================================
__device__ __forceinline__ uint32_t smem_to_u32(const void* smem_ptr) {
    uint32_t addr;
    asm("{ .reg .u64 tmp; cvta.to.shared.u64 tmp, %1; cvt.u32.u64 %0, tmp; }"
        : "=r"(addr) : "l"(smem_ptr));
    return addr;
}

#define LDSM_X4(r, addr) \
    asm volatile("ldmatrix.sync.aligned.m8n8.x4.shared.b16 {%0,%1,%2,%3}, [%4];" \
        : "=r"((r)[0]), "=r"((r)[1]), "=r"((r)[2]), "=r"((r)[3]) : "r"(addr))

#define MMA_BF16(d, a, b0, b1) \
    asm volatile("mma.sync.aligned.m16n8k16.row.col.f32.bf16.bf16.f32 " \
        "{%0,%1,%2,%3}, {%4,%5,%6,%7}, {%8,%9}, {%0,%1,%2,%3};" \
        : "+f"((d)[0]), "+f"((d)[1]), "+f"((d)[2]), "+f"((d)[3]) \
        : "r"((a)[0]), "r"((a)[1]), "r"((a)[2]), "r"((a)[3]), "r"(b0), "r"(b1))

__device__ __forceinline__ void split2(float f0, float f1, uint32_t& hi, uint32_t& lo) {
    __nv_bfloat16 h0 = __float2bfloat16(f0);
    __nv_bfloat16 h1 = __float2bfloat16(f1);
    __nv_bfloat16 l0 = __float2bfloat16(f0 - __bfloat162float(h0));
    __nv_bfloat16 l1 = __float2bfloat16(f1 - __bfloat162float(h1));
    hi = ((uint32_t)__bfloat16_as_ushort(h1) << 16) | (uint32_t)__bfloat16_as_ushort(h0);
    lo = ((uint32_t)__bfloat16_as_ushort(l1) << 16) | (uint32_t)__bfloat16_as_ushort(l0);
}

// ============================================================================
// CSR build: histogram -> single-pass scan -> fill
// ============================================================================
__global__ void hist_kernel(const int* __restrict__ dst_idx, int n_edge) {
    int e = blockIdx.x * blockDim.x + threadIdx.x;
    if (e == 0) g_total = 0;  // consumed only by scan (next launch)
    if (e < n_edge) atomicAdd(&g_cnt[__ldg(dst_idx + e)], 1);
}

__global__ void __launch_bounds__(1024) scan_block_kernel(int n) {
    __shared__ int ssum[1024];
    __shared__ int soff;
    int b = blockIdx.x, t = threadIdx.x;
    int base = b * 4096 + t * 4;
    int v[4], s = 0;
    #pragma unroll
    for (int j = 0; j < 4; j++) {
        v[j] = (base + j < n) ? g_cnt[base + j] : 0;
        s += v[j];
    }
    ssum[t] = s;
    __syncthreads();
    #pragma unroll
    for (int off = 1; off < 1024; off <<= 1) {
        int val = (t >= off) ? ssum[t - off] : 0;
        __syncthreads();
        ssum[t] += val;
        __syncthreads();
    }
    if (t == 1023) soff = atomicAdd(&g_total, ssum[1023]);
    __syncthreads();
    int run = ssum[t] - s + soff;  // absolute exclusive prefix
    #pragma unroll
    for (int j = 0; j < 4; j++) {
        if (base + j < n) { g_rowptr[base + j] = run; g_cursor[base + j] = run; }
        run += v[j];
    }
}

__global__ void fill_kernel(const int* __restrict__ src_idx,
                            const int* __restrict__ dst_idx, int n_edge) {
    int e = blockIdx.x * blockDim.x + threadIdx.x;
    if (e < n_edge) {
        int d = __ldg(dst_idx + e);
        int p = atomicAdd(&g_cursor[d], 1);
        g_csr[p] = __ldg(src_idx + e);
    }
}

// ============================================================================
// convert_w: W1,W2 -> pre-split bf16 hi/lo, packed [kb][n][k].
// 16384 bf16-pairs total; 64 blocks x 256 threads, 1 pair each.
// ============================================================================
__global__ void convert_w_kernel(const float* __restrict__ W1,
                                 const float* __restrict__ W2) {
    int p = blockIdx.x * blockDim.x + threadIdx.x;  // pair index
    if (p >= 2 * 128 * 64) return;
    const float* W = (p >= 8192) ? W2 : W1;
    int rem = p & 8191;
    const float2 v = __ldg(reinterpret_cast<const float2*>(W) + rem);
    uint32_t h, l;
    split2(v.x, v.y, h, l);
    g_bh[p] = h;
    g_bl[p] = l;
}

// ============================================================================
// aggself: one warp per dst row.
//  - independent self gather issued first (extra MLP during CSR loop)
//  - CSR gather-sum (unroll-4), degree-normalize
//  - split both results to bf16 hi/lo, store packed (uint2 per lane)
//  - resets g_cnt for the next graph replay
// ============================================================================
__global__ void __launch_bounds__(256) aggself_kernel(
    const float* __restrict__ x,
    const float* __restrict__ degree,
    const int* __restrict__ self_ids,
    int n_dst)
{
    int t = blockIdx.x * blockDim.x + threadIdx.x;
    int r = t >> 5;
    if (r >= n_dst) return;
    int lane = t & 31;
    const float4* x4 = reinterpret_cast<const float4*>(x);

    // self gather first (independent of CSR chain)
    int sid = __ldg(self_ids + r);
    float4 sv = __ldg(x4 + (size_t)sid * 32 + lane);

    int start = __ldg(&g_rowptr[r]);
    int c = __ldg(&g_cnt[r]);
    __syncwarp();
    if (lane == 0) g_cnt[r] = 0;  // reset for next replay

    float4 acc = make_float4(0.f, 0.f, 0.f, 0.f);
    int e = start, end = start + c;
    for (; e + 3 < end; e += 4) {
        int s0 = __ldg(&g_csr[e]);
        int s1 = __ldg(&g_csr[e + 1]);
        int s2 = __ldg(&g_csr[e + 2]);
        int s3 = __ldg(&g_csr[e + 3]);
        float4 v0 = __ldg(x4 + (size_t)s0 * 32 + lane);
        float4 v1 = __ldg(x4 + (size_t)s1 * 32 + lane);
        float4 v2 = __ldg(x4 + (size_t)s2 * 32 + lane);
        float4 v3 = __ldg(x4 + (size_t)s3 * 32 + lane);
        acc.x += v0.x + v1.x + v2.x + v3.x;
        acc.y += v0.y + v1.y + v2.y + v3.y;
        acc.z += v0.z + v1.z + v2.z + v3.z;
        acc.w += v0.w + v1.w + v2.w + v3.w;
    }
    for (; e < end; e++) {
        int s0 = __ldg(&g_csr[e]);
        float4 v0 = __ldg(x4 + (size_t)s0 * 32 + lane);
        acc.x += v0.x; acc.y += v0.y; acc.z += v0.z; acc.w += v0.w;
    }
    float inv = 1.0f / __ldg(degree + r);
    acc.x *= inv; acc.y *= inv; acc.z *= inv; acc.w *= inv;

    uint32_t h0, l0, h1, l1;
    split2(acc.x, acc.y, h0, l0);
    split2(acc.z, acc.w, h1, l1);
    reinterpret_cast<uint2*>(g_aggh)[(size_t)r * 32 + lane] = make_uint2(h0, h1);
    reinterpret_cast<uint2*>(g_aggl)[(size_t)r * 32 + lane] = make_uint2(l0, l1);

    split2(sv.x, sv.y, h0, l0);
    split2(sv.z, sv.w, h1, l1);
    reinterpret_cast<uint2*>(g_selfh)[(size_t)r * 32 + lane] = make_uint2(h0, h1);
    reinterpret_cast<uint2*>(g_selfl)[(size_t)r * 32 + lane] = make_uint2(l0, l1);
}

// ============================================================================
// GEMM: pure copies (pre-split bf16) + ldmatrix + mma. Zero conversion ALU.
//   out[r,:] = agg_norm[r,:] @ W1^T + x[self_ids[r],:] @ W2^T
// CTA: 256 threads (8 warps, 4x2), output tile 128x128, warp tile 32x64.
// ============================================================================
#define ROWPITCH 272
#define TILE_BYTES (128 * ROWPITCH)  // 34816
#define SM_A_HI 0
#define SM_A_LO (TILE_BYTES)
#define SM_B_HI (2 * TILE_BYTES)
#define SM_B_LO (3 * TILE_BYTES)
#define SMEM_TOTAL (4 * TILE_BYTES)  // 139264

__global__ void __launch_bounds__(256, 1) gemm_kernel(
    float* __restrict__ out, int n_dst)
{
    extern __shared__ char smem[];
    uint32_t smem_base = smem_to_u32(smem);
    int tid = threadIdx.x;
    int wid = tid >> 5;
    int lane = tid & 31;
    int tile = blockIdx.x;

    int warp_m = (wid & 3) * 32;   // 0,32,64,96
    int warp_n = (wid >> 2) * 64;  // 0,64

    float acc[2][8][4];
    #pragma unroll
    for (int i = 0; i < 2; i++)
        #pragma unroll
        for (int j = 0; j < 8; j++)
            #pragma unroll
            for (int q = 0; q < 4; q++) acc[i][j][q] = 0.f;

    // per-lane ldmatrix base offsets
    uint32_t aoff = (uint32_t)(warp_m + (lane & 15)) * ROWPITCH
                  + ((lane & 16) ? 16u : 0u);
    uint32_t boff = (uint32_t)(warp_n + (lane & 7) + ((lane & 16) ? 8 : 0)) * ROWPITCH
                  + ((lane & 8) ? 16u : 0u);

    // copy mapping: row = tid/2, half-row (128B = 8 uint4)
    int lrow = tid >> 1;
    int half = tid & 1;
    uint32_t dstbase = (uint32_t)lrow * ROWPITCH + (uint32_t)half * 128;
    int r = tile * 128 + lrow;
    bool valid = (r < n_dst);
    // per-row uint4 source index: row*16 + half*8
    size_t a_src = (size_t)r * 16 + half * 8;
    size_t b_srcrow = (size_t)lrow * 16 + half * 8;

    const uint4* aggh4  = reinterpret_cast<const uint4*>(g_aggh);
    const uint4* aggl4  = reinterpret_cast<const uint4*>(g_aggl);
    const uint4* selfh4 = reinterpret_cast<const uint4*>(g_selfh);
    const uint4* selfl4 = reinterpret_cast<const uint4*>(g_selfl);
    const uint4* bh4    = reinterpret_cast<const uint4*>(g_bh);
    const uint4* bl4    = reinterpret_cast<const uint4*>(g_bl);
    const uint4 z = make_uint4(0, 0, 0, 0);

    #pragma unroll
    for (int kb = 0; kb < 2; kb++) {
        if (kb) __syncthreads();  // kb0 mma must finish reading smem

        const uint4* ah = kb ? selfh4 : aggh4;
        const uint4* al = kb ? selfl4 : aggl4;
        #pragma unroll
        for (int j = 0; j < 8; j++) {
            uint4 vh = valid ? __ldg(ah + a_src + j) : z;
            uint4 vl = valid ? __ldg(al + a_src + j) : z;
            *reinterpret_cast<uint4*>(smem + SM_A_HI + dstbase + j * 16) = vh;
            *reinterpret_cast<uint4*>(smem + SM_A_LO + dstbase + j * 16) = vl;
        }
        size_t b_src = (size_t)kb * 2048 + b_srcrow;
        #pragma unroll
        for (int j = 0; j < 8; j++) {
            uint4 vh = __ldg(bh4 + b_src + j);
            uint4 vl = __ldg(bl4 + b_src + j);
            *reinterpret_cast<uint4*>(smem + SM_B_HI + dstbase + j * 16) = vh;
            *reinterpret_cast<uint4*>(smem + SM_B_LO + dstbase + j * 16) = vl;
        }
        __syncthreads();

        // ---- 3 passes x 8 k-steps of mma ----
        #pragma unroll
        for (int p = 0; p < 3; p++) {
            uint32_t abase = smem_base + (p == 1 ? SM_A_LO : SM_A_HI) + aoff;
            uint32_t bbase = smem_base + (p == 2 ? SM_B_LO : SM_B_HI) + boff;
            #pragma unroll
            for (int ks = 0; ks < 8; ks++) {
                uint32_t a0r[4], a1r[4];
                LDSM_X4(a0r, abase + ks * 32);
                LDSM_X4(a1r, abase + 16 * ROWPITCH + ks * 32);
                #pragma unroll
                for (int nf2 = 0; nf2 < 4; nf2++) {
                    uint32_t br[4];
                    LDSM_X4(br, bbase + nf2 * 16 * ROWPITCH + ks * 32);
                    MMA_BF16(acc[0][2 * nf2],     a0r, br[0], br[1]);
                    MMA_BF16(acc[0][2 * nf2 + 1], a0r, br[2], br[3]);
                    MMA_BF16(acc[1][2 * nf2],     a1r, br[0], br[1]);
                    MMA_BF16(acc[1][2 * nf2 + 1], a1r, br[2], br[3]);
                }
            }
        }
    }

    // ---- epilogue: c-frag (m = lane/4 + {0,8}, n = 2*(lane%4) + {0,1}) ----
    int rbase = tile * 128 + warp_m + (lane >> 2);
    int cbase = warp_n + (lane & 3) * 2;
    #pragma unroll
    for (int mf = 0; mf < 2; mf++) {
        #pragma unroll
        for (int nf = 0; nf < 8; nf++) {
            int r0 = rbase + mf * 16;
            int c  = cbase + nf * 8;
            if (r0 < n_dst) {
                float2* p = reinterpret_cast<float2*>(out + (size_t)r0 * DFEAT + c);
                *p = make_float2(acc[mf][nf][0], acc[mf][nf][1]);
            }
            if (r0 + 8 < n_dst) {
                float2* p = reinterpret_cast<float2*>(out + (size_t)(r0 + 8) * DFEAT + c);
                *p = make_float2(acc[mf][nf][2], acc[mf][nf][3]);
            }
        }
    }
}

// ============================================================================
// kernel_launch
// inputs: 0:x [N_SRC*128 f32]  1:W1 [128*128 f32]  2:W2 [128*128 f32]
//         3:degree [N_DST f32] 4:src_idx [N_EDGE i32] 5:dst_idx [N_EDGE i32]
//         6:self_ids [N_DST i32]       output: [N_DST*128 f32]
// ============================================================================
extern "C" void kernel_launch(void* const* d_in, const int* in_sizes, int n_in,
                              void* d_out, int out_size) {
    const float* x        = (const float*)d_in[0];
    const float* W1       = (const float*)d_in[1];
    const float* W2       = (const float*)d_in[2];
    const float* degree   = (const float*)d_in[3];
    const int*   src_idx  = (const int*)d_in[4];
    const int*   dst_idx  = (const int*)d_in[5];
    const int*   self_ids = (const int*)d_in[6];
    float* out = (float*)d_out;

    int n_dst  = in_sizes[3];
    int n_edge = in_sizes[4];

    // CSR build (g_cnt zeroed by aggself_kernel of the previous run / static init)
    hist_kernel<<<(n_edge + 255) / 256, 256>>>(dst_idx, n_edge);
    int nblocks = (n_dst + 4095) / 4096;
    scan_block_kernel<<<nblocks, 1024>>>(n_dst);
    fill_kernel<<<(n_edge + 255) / 256, 256>>>(src_idx, dst_idx, n_edge);

    // weight pre-split (tiny, once per launch)
    convert_w_kernel<<<64, 256>>>(W1, W2);

    // aggregation + self-path gather + bf16 split (1 warp / dst row)
    long long tot = (long long)n_dst * 32;
    aggself_kernel<<<(int)((tot + 255) / 256), 256>>>(x, degree, self_ids, n_dst);

    // conversion-free GEMM
    static bool attr_set = false;
    if (!attr_set) {
        cudaFuncSetAttribute(gemm_kernel,
                             cudaFuncAttributeMaxDynamicSharedMemorySize, SMEM_TOTAL);
        attr_set = true;
    }
    gemm_kernel<<<(n_dst + 127) / 128, 256, SMEM_TOTAL>>>(out, n_dst);
}